// round 2
// baseline (speedup 1.0000x reference)
#include <cuda_runtime.h>
#include <cuda_bf16.h>
#include <math.h>

#define NB 4096
#define NL 8192
#define NT 256
#define CHUNK 2048
#define NCH (NL / CHUNK)          // 4 chunks per row
#define NSLOT (NB * NCH)          // 16384 partial slots

// Per-tile partials (scratch). Slot = row*NCH + chunk.
__device__ float    g_bce[NSLOT];
__device__ int      g_tp[NSLOT];
__device__ int      g_tn[NSLOT];
__device__ int      g_gp[NSLOT];
__device__ unsigned g_count = 0;  // last-block-done counter; reset to 0 by last block each launch

__device__ __forceinline__ void acc_elem(float p, float t,
                                         float& bce, int& tp, int& tn, int& gp) {
    if (!isfinite(p)) p = 0.0f;        // torch.where(isnan|isinf, 0, pred)
    bool tb = (t > 0.0f);              // truth is exactly 0.0 or 1.0
    float x  = tb ? p : (1.0f - p);    // select the live log branch
    float lg = fmaxf(__logf(x), -100.0f);  // __logf(0) = -inf -> clamped
    bce -= lg;
    bool pb = (p > 0.5f);
    tp += (int)(pb && tb);
    tn += (int)(!pb && !tb);
    gp += (int)tb;
}

__global__ void __launch_bounds__(NT) fused_kernel(const float* __restrict__ pred,
                                                   const float* __restrict__ truth,
                                                   const int*   __restrict__ lengths,
                                                   float* __restrict__ out,
                                                   int out_size) {
    const int row   = blockIdx.x >> 2;        // NCH == 4
    const int chunk = blockIdx.x & (NCH - 1);
    const int len   = __ldg(lengths + row);
    const int start = chunk * CHUNK;
    const int v     = min(len - start, CHUNK);  // valid elems in this tile (may be <= 0)

    float bce = 0.0f;
    int tp = 0, tn = 0, gp = 0;

    if (v > 0) {
        const size_t off = (size_t)row * NL + start;
        const float4* __restrict__ p4 = reinterpret_cast<const float4*>(pred + off);
        const float4* __restrict__ t4 = reinterpret_cast<const float4*>(truth + off);
        const int n4 = v >> 2;
        for (int i = threadIdx.x; i < n4; i += NT) {   // <= 2 iterations
            float4 p = p4[i];
            float4 t = t4[i];
            acc_elem(p.x, t.x, bce, tp, tn, gp);
            acc_elem(p.y, t.y, bce, tp, tn, gp);
            acc_elem(p.z, t.z, bce, tp, tn, gp);
            acc_elem(p.w, t.w, bce, tp, tn, gp);
        }
        const int base = n4 << 2;
        if ((int)threadIdx.x < v - base) {
            acc_elem(pred[off + base + threadIdx.x],
                     truth[off + base + threadIdx.x], bce, tp, tn, gp);
        }
    }

    // ---- block reduce into this tile's slot ----
    #pragma unroll
    for (int s = 16; s > 0; s >>= 1) {
        bce += __shfl_down_sync(0xffffffffu, bce, s);
        tp  += __shfl_down_sync(0xffffffffu, tp,  s);
        tn  += __shfl_down_sync(0xffffffffu, tn,  s);
        gp  += __shfl_down_sync(0xffffffffu, gp,  s);
    }
    __shared__ float s_bce[NT / 32];
    __shared__ int   s_tp[NT / 32], s_tn[NT / 32], s_gp[NT / 32];
    const int wid = threadIdx.x >> 5, lid = threadIdx.x & 31;
    if (lid == 0) { s_bce[wid] = bce; s_tp[wid] = tp; s_tn[wid] = tn; s_gp[wid] = gp; }
    __syncthreads();

    __shared__ bool isLast;
    if (threadIdx.x == 0) {
        float b = 0.0f; int a = 0, c = 0, d = 0;
        #pragma unroll
        for (int w = 0; w < NT / 32; w++) { b += s_bce[w]; a += s_tp[w]; c += s_tn[w]; d += s_gp[w]; }
        g_bce[blockIdx.x] = b; g_tp[blockIdx.x] = a; g_tn[blockIdx.x] = c; g_gp[blockIdx.x] = d;
        __threadfence();
        unsigned t = atomicAdd(&g_count, 1u);
        isLast = (t == (unsigned)(NSLOT - 1));
    }
    __syncthreads();
    if (!isLast) return;
    __threadfence();   // acquire all partials

    // ---- finalize (single surviving block, partials are L2-hot) ----
    float loss = 0.0f;
    int Tp = 0, Tn = 0, Gp = 0, Valid = 0;   // totals fit in int (max ~33.5M)
    for (int r = threadIdx.x; r < NB; r += NT) {   // 16 iterations
        const int len = __ldg(lengths + r);
        float4 b = *reinterpret_cast<const float4*>(&g_bce[r * NCH]);
        int4  a1 = *reinterpret_cast<const int4*>(&g_tp[r * NCH]);
        int4  a2 = *reinterpret_cast<const int4*>(&g_tn[r * NCH]);
        int4  a3 = *reinterpret_cast<const int4*>(&g_gp[r * NCH]);
        if (len > 0) loss += (b.x + b.y + b.z + b.w) / (float)len;
        Tp += a1.x + a1.y + a1.z + a1.w;
        Tn += a2.x + a2.y + a2.z + a2.w;
        Gp += a3.x + a3.y + a3.z + a3.w;
        Valid += len;
    }
    #pragma unroll
    for (int s = 16; s > 0; s >>= 1) {
        loss  += __shfl_down_sync(0xffffffffu, loss,  s);
        Tp    += __shfl_down_sync(0xffffffffu, Tp,    s);
        Tn    += __shfl_down_sync(0xffffffffu, Tn,    s);
        Gp    += __shfl_down_sync(0xffffffffu, Gp,    s);
        Valid += __shfl_down_sync(0xffffffffu, Valid, s);
    }
    __shared__ float fl[NT / 32];
    __shared__ int   ftp[NT / 32], ftn[NT / 32], fgp[NT / 32], fv[NT / 32];
    if (lid == 0) { fl[wid] = loss; ftp[wid] = Tp; ftn[wid] = Tn; fgp[wid] = Gp; fv[wid] = Valid; }
    __syncthreads();
    if (threadIdx.x == 0) {
        float L = 0.0f; int TP = 0, TN = 0, GP = 0, V = 0;
        #pragma unroll
        for (int w = 0; w < NT / 32; w++) { L += fl[w]; TP += ftp[w]; TN += ftn[w]; GP += fgp[w]; V += fv[w]; }
        int GN = V - GP;
        if (GP < 1) GP = 1;
        if (GN < 1) GN = 1;
        out[0] = L / (float)NB;
        if (out_size > 1) out[1] = ((float)TP / (float)GP) * ((float)TN / (float)GN);
        g_count = 0;   // reset for next graph replay
    }
}

extern "C" void kernel_launch(void* const* d_in, const int* in_sizes, int n_in,
                              void* d_out, int out_size) {
    const float* pred    = (const float*)d_in[0];
    const float* truth   = (const float*)d_in[1];
    const int*   lengths = (const int*)d_in[2];
    float* out = (float*)d_out;

    fused_kernel<<<NSLOT, NT>>>(pred, truth, lengths, out, out_size);
}

// round 3
// speedup vs baseline: 1.3545x; 1.3545x over previous
#include <cuda_runtime.h>
#include <cuda_bf16.h>
#include <math.h>

#define NB 4096
#define NL 8192
#define NT 256
#define NBLK 1184                  // 8 * 148 SMs
#define N4 (NB * NL / 4)           // 8388608 float4 pairs
#define R4 (NL / 4)                // 2048 float4 per row

// Per-block partials + completion counter (scratch).
__device__ float    g_loss[NBLK];
__device__ int      g_tp[NBLK];
__device__ int      g_tn[NBLK];
__device__ int      g_gp[NBLK];
__device__ unsigned g_count = 0;

__device__ __forceinline__ void acc_elem(float p, float t, float inv_len,
                                         float& loss, int& tp, int& tn, int& gp) {
    // torch.where(isnan|isinf, 0, pred): p-p==0 iff p finite
    p = (p - p == 0.0f) ? p : 0.0f;
    bool tb = (t > 0.0f);                   // truth is exactly 0.0 or 1.0
    float x  = tb ? p : (1.0f - p);
    float lg = fmaxf(__logf(x), -100.0f);   // __logf(0) = -inf -> clamp
    loss = __fmaf_rn(lg, inv_len, loss);    // bce contribution already / len (negate at end)
    bool pb = (p > 0.5f);
    tp += (int)(pb && tb);
    tn += (int)(!pb && !tb);
    gp += (int)tb;
}

__global__ void __launch_bounds__(NT) main_kernel(const float* __restrict__ pred,
                                                  const float* __restrict__ truth,
                                                  const int*   __restrict__ lengths,
                                                  float* __restrict__ out,
                                                  int out_size) {
    const int tid = blockIdx.x * NT + threadIdx.x;
    const int T   = NBLK * NT;

    const float4* __restrict__ p4 = reinterpret_cast<const float4*>(pred);
    const float4* __restrict__ t4 = reinterpret_cast<const float4*>(truth);

    float loss = 0.0f;             // sum of -bce/len contributions (sign flipped at end)
    int tp = 0, tn = 0, gp = 0;

    #pragma unroll 2
    for (int i = tid; i < N4; i += T) {
        const int row = i >> 11;                // R4 = 2048
        const int col = (i & (R4 - 1)) << 2;    // element index of .x
        const int len = __ldg(lengths + row);
        const int v   = len - col;              // valid elems in this float4 (cap 4)
        if (v > 0) {
            float4 p = p4[i];
            float4 t = t4[i];
            const float inv_len = __fdividef(1.0f, (float)len);
            acc_elem(p.x, t.x, inv_len, loss, tp, tn, gp);
            if (v > 1) acc_elem(p.y, t.y, inv_len, loss, tp, tn, gp);
            if (v > 2) acc_elem(p.z, t.z, inv_len, loss, tp, tn, gp);
            if (v > 3) acc_elem(p.w, t.w, inv_len, loss, tp, tn, gp);
        }
    }

    // ---- block reduce ----
    #pragma unroll
    for (int s = 16; s > 0; s >>= 1) {
        loss += __shfl_down_sync(0xffffffffu, loss, s);
        tp   += __shfl_down_sync(0xffffffffu, tp,   s);
        tn   += __shfl_down_sync(0xffffffffu, tn,   s);
        gp   += __shfl_down_sync(0xffffffffu, gp,   s);
    }
    __shared__ float s_l[NT / 32];
    __shared__ int   s_tp[NT / 32], s_tn[NT / 32], s_gp[NT / 32];
    const int wid = threadIdx.x >> 5, lid = threadIdx.x & 31;
    if (lid == 0) { s_l[wid] = loss; s_tp[wid] = tp; s_tn[wid] = tn; s_gp[wid] = gp; }
    __syncthreads();

    __shared__ bool isLast;
    if (threadIdx.x == 0) {
        float L = 0.0f; int a = 0, b = 0, c = 0;
        #pragma unroll
        for (int w = 0; w < NT / 32; w++) { L += s_l[w]; a += s_tp[w]; b += s_tn[w]; c += s_gp[w]; }
        g_loss[blockIdx.x] = L; g_tp[blockIdx.x] = a; g_tn[blockIdx.x] = b; g_gp[blockIdx.x] = c;
        __threadfence();
        unsigned t = atomicAdd(&g_count, 1u);
        isLast = (t == (unsigned)(NBLK - 1));
    }
    __syncthreads();
    if (!isLast) return;
    __threadfence();

    // ---- finalize in the last block (partials L2-hot) ----
    float L = 0.0f;
    int Tp = 0, Tn = 0, Gp = 0;
    for (int i = threadIdx.x; i < NBLK; i += NT) {   // <= 5 iterations
        L += g_loss[i]; Tp += g_tp[i]; Tn += g_tn[i]; Gp += g_gp[i];
    }
    int Valid = 0;
    for (int r = threadIdx.x; r < NB; r += NT)        // 16 iterations
        Valid += __ldg(lengths + r);

    #pragma unroll
    for (int s = 16; s > 0; s >>= 1) {
        L     += __shfl_down_sync(0xffffffffu, L,     s);
        Tp    += __shfl_down_sync(0xffffffffu, Tp,    s);
        Tn    += __shfl_down_sync(0xffffffffu, Tn,    s);
        Gp    += __shfl_down_sync(0xffffffffu, Gp,    s);
        Valid += __shfl_down_sync(0xffffffffu, Valid, s);
    }
    __shared__ float fl[NT / 32];
    __shared__ int   f1[NT / 32], f2[NT / 32], f3[NT / 32], f4[NT / 32];
    if (lid == 0) { fl[wid] = L; f1[wid] = Tp; f2[wid] = Tn; f3[wid] = Gp; f4[wid] = Valid; }
    __syncthreads();
    if (threadIdx.x == 0) {
        float LL = 0.0f; int TP = 0, TN = 0, GP = 0, V = 0;
        #pragma unroll
        for (int w = 0; w < NT / 32; w++) { LL += fl[w]; TP += f1[w]; TN += f2[w]; GP += f3[w]; V += f4[w]; }
        int GN = V - GP;
        if (GP < 1) GP = 1;
        if (GN < 1) GN = 1;
        out[0] = -LL / (float)NB;   // flip sign: we accumulated +log terms
        if (out_size > 1) out[1] = ((float)TP / (float)GP) * ((float)TN / (float)GN);
        g_count = 0;                // reset for next graph replay
    }
}

extern "C" void kernel_launch(void* const* d_in, const int* in_sizes, int n_in,
                              void* d_out, int out_size) {
    const float* pred    = (const float*)d_in[0];
    const float* truth   = (const float*)d_in[1];
    const int*   lengths = (const int*)d_in[2];
    float* out = (float*)d_out;

    main_kernel<<<NBLK, NT>>>(pred, truth, lengths, out, out_size);
}